// round 14
// baseline (speedup 1.0000x reference)
#include <cuda_runtime.h>
#include <math.h>
#include <stdint.h>

#define Bn   128
#define Tn   400
#define Vn   50000
#define EPSf 1e-12f

// ---- output layout (floats): concat of reference returns ----
#define O_FINAL 0
#define O_H     6400000
#define O_C     6465536
#define O_CT    6531072
#define O_ATTN  6662144
#define O_PGEN  6713344
#define O_COV   6713472

// ---- scratch ----
#define OFF_XIN    0        // [128,1152]
#define OFF_X      147456   // [128,128]
#define OFF_GATES  163840   // [128,2048]
#define OFF_STHAT  425984   // [128,1024]
#define OFF_DECFEA 557056   // [128,1024]
#define OFF_SCORES 688128   // [128,400]
#define OFF_HCT    739328   // [128,1536]
#define OFF_OUT1   935936   // [128,512]
#define SCRATCH_FLOATS 1001472

__device__ float g_scratch[SCRATCH_FLOATS];

__device__ __forceinline__ float warpReduceSum(float v) {
#pragma unroll
    for (int o = 16; o > 0; o >>= 1) v += __shfl_xor_sync(0xffffffffu, v, o);
    return v;
}
__device__ __forceinline__ float warpReduceMax(float v) {
#pragma unroll
    for (int o = 16; o > 0; o >>= 1) v = fmaxf(v, __shfl_xor_sync(0xffffffffu, v, o));
    return v;
}
__device__ __forceinline__ float sigmoidf_(float x) { return 1.f / (1.f + expf(-x)); }

__device__ __forceinline__ uint32_t f2tf32(float f) {
    uint32_t u;
    asm("cvt.rna.tf32.f32 %0, %1;" : "=r"(u) : "f"(f));
    return u;
}

__device__ __forceinline__ void mma_tf32(float* c, const uint32_t* a, const uint32_t* b) {
    asm("mma.sync.aligned.m16n8k8.row.col.f32.tf32.tf32.f32 "
        "{%0,%1,%2,%3}, {%4,%5,%6,%7}, {%8,%9}, {%0,%1,%2,%3};"
        : "+f"(c[0]), "+f"(c[1]), "+f"(c[2]), "+f"(c[3])
        : "r"(a[0]), "r"(a[1]), "r"(a[2]), "r"(a[3]), "r"(b[0]), "r"(b[1]));
}

// ================= tf32 tensor-core GEMM =================
// C[128, N] = A[128, K](lda) @ B[N, K]^T + bias1 + bias2 (+ C if acc)
// M = 128 always (1 block in M). grid.x = N tiles of (WN*32).
// 2 warps along M (64 rows each), WN warps along N (32 cols each).
// K must be a multiple of 32.
template<int WN>
__global__ void __launch_bounds__(WN * 64) k_mma(
        const float* __restrict__ A, const float* __restrict__ B,
        const float* __restrict__ bias1, const float* __restrict__ bias2,
        float* __restrict__ C, int N, int K, int lda, int ldc, int accFlag) {
    constexpr int NTHR = WN * 64;
    constexpr int TN   = WN * 32;
    constexpr int AF4  = 1024 / NTHR;       // A float4s per thread per chunk
    constexpr int BF4  = (TN * 8) / NTHR;   // B float4s per thread per chunk

    extern __shared__ uint32_t sm[];
    uint32_t* As = sm;                      // [2][128][36]
    uint32_t* Bs = sm + 2 * 128 * 36;       // [2][TN][36]

    const int tid  = threadIdx.x;
    const int wid  = tid >> 5, lane = tid & 31;
    const int g    = lane >> 2, t = lane & 3;
    const int n0   = blockIdx.x * TN;
    const int mw   = (wid / WN) * 64;
    const int nw   = (wid % WN) * 32;

    float acc[4][4][4] = {};
    float4 apf[AF4], bpf[BF4];

    const int nchunks = K >> 5;

#define GLOAD(KC)                                                              \
    {                                                                          \
        const float* Ap = A + (KC) * 32;                                       \
        _Pragma("unroll")                                                      \
        for (int i = 0; i < AF4; i++) {                                        \
            int e = tid + i * NTHR;                                            \
            int r = e >> 3, c4 = (e & 7) * 4;                                  \
            apf[i] = *(const float4*)(Ap + (long long)r * lda + c4);           \
        }                                                                      \
        const float* Bp = B + (KC) * 32;                                       \
        _Pragma("unroll")                                                      \
        for (int i = 0; i < BF4; i++) {                                        \
            int e = tid + i * NTHR;                                            \
            int r = e >> 3, c4 = (e & 7) * 4;                                  \
            int rg = n0 + r;                                                   \
            bpf[i] = (rg < N) ? *(const float4*)(Bp + (long long)rg * K + c4)  \
                              : make_float4(0.f, 0.f, 0.f, 0.f);               \
        }                                                                      \
    }

#define SSTORE(BUF)                                                            \
    {                                                                          \
        uint32_t* Asb = As + (BUF) * (128 * 36);                               \
        _Pragma("unroll")                                                      \
        for (int i = 0; i < AF4; i++) {                                        \
            int e = tid + i * NTHR;                                            \
            int r = e >> 3, c4 = (e & 7) * 4;                                  \
            uint4 u = make_uint4(f2tf32(apf[i].x), f2tf32(apf[i].y),           \
                                 f2tf32(apf[i].z), f2tf32(apf[i].w));          \
            *(uint4*)(Asb + r * 36 + c4) = u;                                  \
        }                                                                      \
        uint32_t* Bsb = Bs + (BUF) * (TN * 36);                                \
        _Pragma("unroll")                                                      \
        for (int i = 0; i < BF4; i++) {                                        \
            int e = tid + i * NTHR;                                            \
            int r = e >> 3, c4 = (e & 7) * 4;                                  \
            uint4 u = make_uint4(f2tf32(bpf[i].x), f2tf32(bpf[i].y),           \
                                 f2tf32(bpf[i].z), f2tf32(bpf[i].w));          \
            *(uint4*)(Bsb + r * 36 + c4) = u;                                  \
        }                                                                      \
    }

    GLOAD(0);
    SSTORE(0);
    __syncthreads();

    int buf = 0;
    for (int kc = 0; kc < nchunks; kc++) {
        bool more = (kc + 1 < nchunks);
        if (more) GLOAD(kc + 1);

        const uint32_t* Asb = As + buf * (128 * 36);
        const uint32_t* Bsb = Bs + buf * (TN * 36);
#pragma unroll
        for (int kk = 0; kk < 32; kk += 8) {
            uint32_t af[4][4], bf[4][2];
#pragma unroll
            for (int mt = 0; mt < 4; mt++) {
                const uint32_t* p = Asb + (mw + mt * 16 + g) * 36 + kk + t;
                af[mt][0] = p[0];
                af[mt][2] = p[4];
                af[mt][1] = p[8 * 36];
                af[mt][3] = p[8 * 36 + 4];
            }
#pragma unroll
            for (int nt = 0; nt < 4; nt++) {
                const uint32_t* p = Bsb + (nw + nt * 8 + g) * 36 + kk + t;
                bf[nt][0] = p[0];
                bf[nt][1] = p[4];
            }
#pragma unroll
            for (int mt = 0; mt < 4; mt++)
#pragma unroll
                for (int nt = 0; nt < 4; nt++)
                    mma_tf32(acc[mt][nt], af[mt], bf[nt]);
        }

        if (more) {
            SSTORE(buf ^ 1);
            __syncthreads();
        }
        buf ^= 1;
    }

    // epilogue
#pragma unroll
    for (int mt = 0; mt < 4; mt++) {
        int r = mw + mt * 16 + g;
#pragma unroll
        for (int nt = 0; nt < 4; nt++) {
            int c = n0 + nw + nt * 8 + 2 * t;
            if (c + 1 < N) {
                float b0 = (bias1 ? bias1[c] : 0.f) + (bias2 ? bias2[c] : 0.f);
                float b1 = (bias1 ? bias1[c + 1] : 0.f) + (bias2 ? bias2[c + 1] : 0.f);
                long long i0 = (long long)r * ldc + c;
                long long i1 = (long long)(r + 8) * ldc + c;
                float2 v0 = make_float2(acc[mt][nt][0] + b0, acc[mt][nt][1] + b1);
                float2 v1 = make_float2(acc[mt][nt][2] + b0, acc[mt][nt][3] + b1);
                if (accFlag) {
                    float2 o0 = *(float2*)&C[i0], o1 = *(float2*)&C[i1];
                    v0.x += o0.x; v0.y += o0.y; v1.x += o1.x; v1.y += o1.y;
                }
                *(float2*)&C[i0] = v0;
                *(float2*)&C[i1] = v1;
            } else if (c < N) {
                float b0 = (bias1 ? bias1[c] : 0.f) + (bias2 ? bias2[c] : 0.f);
                long long i0 = (long long)r * ldc + c;
                long long i1 = (long long)(r + 8) * ldc + c;
                float v0 = acc[mt][nt][0] + b0, v1 = acc[mt][nt][2] + b0;
                if (accFlag) { v0 += C[i0]; v1 += C[i1]; }
                C[i0] = v0;
                C[i1] = v1;
            }
        }
    }
#undef GLOAD
#undef SSTORE
}

// ---- K1: xin = concat(c_t_1, emb[y]) ----
__global__ void k_build_xin(const int* __restrict__ y, const float* __restrict__ ct1,
                            const float* __restrict__ emb, float* __restrict__ xin) {
    int b = blockIdx.x;
    int yy = y[b];
    for (int i = threadIdx.x; i < 1152; i += blockDim.x)
        xin[b * 1152 + i] = (i < 1024) ? ct1[b * 1024 + i] : emb[yy * 128 + (i - 1024)];
}

// ---- LSTM cell elementwise ----
__global__ void k_lstm(const float* __restrict__ gates, const float* __restrict__ c0,
                       float* __restrict__ out, float* __restrict__ sthat,
                       float* __restrict__ hct) {
    int b = blockIdx.x, j = threadIdx.x;   // 512 threads
    const float* g = gates + b * 2048;
    float ig = g[j], fg = g[512 + j], gg = g[1024 + j], og = g[1536 + j];
    float c = sigmoidf_(fg) * c0[b * 512 + j] + sigmoidf_(ig) * tanhf(gg);
    float h = sigmoidf_(og) * tanhf(c);
    out[O_H + b * 512 + j] = h;
    out[O_C + b * 512 + j] = c;
    sthat[b * 1024 + j] = h;
    sthat[b * 1024 + 512 + j] = c;
    hct[b * 1536 + j] = h;
}

// ---- attention scores: warp-per-t, no block syncs in the hot loop ----
__global__ __launch_bounds__(256) void k_attn_scores(const float* __restrict__ encf,
                                                     const float* __restrict__ decfea,
                                                     const float* __restrict__ cov,
                                                     const float* __restrict__ Wc,
                                                     const float* __restrict__ vw,
                                                     float* __restrict__ scores) {
    __shared__ float4 df[256], wc[256], vv[256];
    int b = blockIdx.x, tid = threadIdx.x;
    df[tid] = ((const float4*)(decfea + b * 1024))[tid];
    wc[tid] = ((const float4*)Wc)[tid];
    vv[tid] = ((const float4*)vw)[tid];
    __syncthreads();
    int w = tid >> 5, lane = tid & 31;
#pragma unroll
    for (int i = 0; i < 2; i++) {
        int tt = blockIdx.y * 16 + w * 2 + i;
        float cv = cov[b * 400 + tt];
        const float4* ef = (const float4*)(encf + ((long long)b * 400 + tt) * 1024);
        float local = 0.f;
#pragma unroll
        for (int j = 0; j < 8; j++) {
            int idx = lane + j * 32;
            float4 e4 = ef[idx];
            float4 d4 = df[idx], w4 = wc[idx], v4 = vv[idx];
            local += tanhf(e4.x + d4.x + cv * w4.x) * v4.x;
            local += tanhf(e4.y + d4.y + cv * w4.y) * v4.y;
            local += tanhf(e4.z + d4.z + cv * w4.z) * v4.z;
            local += tanhf(e4.w + d4.w + cv * w4.w) * v4.w;
        }
        local = warpReduceSum(local);
        if (lane == 0) scores[b * 400 + tt] = local;
    }
}

// ---- softmax over T, masking, renorm, coverage update ----
__global__ __launch_bounds__(128) void k_attn_softmax(const float* __restrict__ scores,
                                                      const float* __restrict__ mask,
                                                      const float* __restrict__ cov,
                                                      float* __restrict__ out) {
    __shared__ float sc[400];
    __shared__ float red[4];
    int b = blockIdx.x, tid = threadIdx.x;
    float mx = -1e30f;
    for (int t = tid; t < 400; t += 128) {
        float v = scores[b * 400 + t];
        sc[t] = v;
        mx = fmaxf(mx, v);
    }
    mx = warpReduceMax(mx);
    if ((tid & 31) == 0) red[tid >> 5] = mx;
    __syncthreads();
    mx = fmaxf(fmaxf(red[0], red[1]), fmaxf(red[2], red[3]));
    __syncthreads();

    float s = 0.f;
    for (int t = tid; t < 400; t += 128) {
        float e = expf(sc[t] - mx);
        sc[t] = e;
        s += e;
    }
    s = warpReduceSum(s);
    if ((tid & 31) == 0) red[tid >> 5] = s;
    __syncthreads();
    float denom = red[0] + red[1] + red[2] + red[3];
    __syncthreads();

    float s2 = 0.f;
    for (int t = tid; t < 400; t += 128) {
        float m = sc[t] / denom * mask[b * 400 + t];
        sc[t] = m;
        s2 += m;
    }
    s2 = warpReduceSum(s2);
    if ((tid & 31) == 0) red[tid >> 5] = s2;
    __syncthreads();
    float denom2 = red[0] + red[1] + red[2] + red[3] + EPSf;

    for (int t = tid; t < 400; t += 128) {
        float a = sc[t] / denom2;
        out[O_ATTN + b * 400 + t] = a;
        out[O_COV + b * 400 + t] = cov[b * 400 + t] + a;
    }
}

// ---- context vector ----
__global__ __launch_bounds__(256) void k_context(const float* __restrict__ encout,
                                                 const float* __restrict__ outbuf,
                                                 float* __restrict__ out,
                                                 float* __restrict__ hct) {
    __shared__ float at[400];
    int b = blockIdx.x;
    for (int i = threadIdx.x; i < 400; i += 256) at[i] = outbuf[O_ATTN + b * 400 + i];
    __syncthreads();
    int n = blockIdx.y * 256 + threadIdx.x;
    const float* ep = encout + (long long)b * 400 * 1024 + n;
    float a0 = 0.f, a1 = 0.f, a2 = 0.f, a3 = 0.f;
    for (int t = 0; t < 400; t += 4) {
        a0 += at[t + 0] * ep[(t + 0) * 1024];
        a1 += at[t + 1] * ep[(t + 1) * 1024];
        a2 += at[t + 2] * ep[(t + 2) * 1024];
        a3 += at[t + 3] * ep[(t + 3) * 1024];
    }
    float acc = (a0 + a1) + (a2 + a3);
    out[O_CT + b * 1024 + n] = acc;
    hct[b * 1536 + 512 + n] = acc;
}

// ---- pointer-generator gate ----
__global__ __launch_bounds__(256) void k_pgen(const float* __restrict__ outbuf,
                                              const float* __restrict__ sthat,
                                              const float* __restrict__ x,
                                              const float* __restrict__ Wpg,
                                              const float* __restrict__ bpg,
                                              float* __restrict__ out) {
    __shared__ float red[8];
    int b = blockIdx.x, tid = threadIdx.x;
    float local = 0.f;
    for (int i = tid; i < 2176; i += 256) {
        float v;
        if (i < 1024)       v = outbuf[O_CT + b * 1024 + i];
        else if (i < 2048)  v = sthat[b * 1024 + (i - 1024)];
        else                v = x[b * 128 + (i - 2048)];
        local += Wpg[i] * v;
    }
    local = warpReduceSum(local);
    if ((tid & 31) == 0) red[tid >> 5] = local;
    __syncthreads();
    if (tid == 0) {
        float s = 0.f;
#pragma unroll
        for (int w = 0; w < 8; w++) s += red[w];
        out[O_PGEN + b] = sigmoidf_(s + bpg[0]);
    }
}

// ---- vocab softmax: online max+sum (single read pass) + scale pass ----
__global__ __launch_bounds__(256) void k_vocab_softmax(float* __restrict__ out) {
    __shared__ float rm[8], rs[8];
    int b = blockIdx.x, tid = threadIdx.x;
    float* row = out + (long long)b * Vn;

    float m = -1e30f, s = 0.f;
    for (int i = tid; i < Vn; i += 256) {
        float v = row[i];
        if (v > m) { s *= expf(m - v); m = v; }
        s += expf(v - m);
    }
#pragma unroll
    for (int o = 16; o > 0; o >>= 1) {
        float m2 = __shfl_xor_sync(0xffffffffu, m, o);
        float s2 = __shfl_xor_sync(0xffffffffu, s, o);
        float M = fmaxf(m, m2);
        s = s * expf(m - M) + s2 * expf(m2 - M);
        m = M;
    }
    if ((tid & 31) == 0) { rm[tid >> 5] = m; rs[tid >> 5] = s; }
    __syncthreads();
    float M = rm[0];
#pragma unroll
    for (int w = 1; w < 8; w++) M = fmaxf(M, rm[w]);
    float S = 0.f;
#pragma unroll
    for (int w = 0; w < 8; w++) S += rs[w] * expf(rm[w] - M);

    float scale = out[O_PGEN + b] / S;
    for (int i = tid; i < Vn; i += 256) row[i] = expf(row[i] - M) * scale;
}

// ---- pointer scatter-add ----
__global__ void k_scatter(const int* __restrict__ ebev, const float* __restrict__ outbuf,
                          float* __restrict__ out) {
    int idx = blockIdx.x * blockDim.x + threadIdx.x;
    if (idx >= Bn * Tn) return;
    int b = idx / Tn;
    float add = (1.f - outbuf[O_PGEN + b]) * outbuf[O_ATTN + idx];
    atomicAdd(&out[(long long)b * Vn + ebev[idx]], add);
}

extern "C" void kernel_launch(void* const* d_in, const int* in_sizes, int n_in,
                              void* d_out, int out_size) {
    const int*   y      = (const int*)d_in[0];
    const float* h0     = (const float*)d_in[1];
    const float* c0     = (const float*)d_in[2];
    const float* ct1    = (const float*)d_in[3];
    const float* encout = (const float*)d_in[4];
    const float* encf   = (const float*)d_in[5];
    const float* mask   = (const float*)d_in[6];
    const int*   ebev   = (const int*)d_in[7];
    const float* cov    = (const float*)d_in[8];
    const float* emb    = (const float*)d_in[9];
    const float* Wc     = (const float*)d_in[10];
    const float* Wdp    = (const float*)d_in[11];
    const float* bdp    = (const float*)d_in[12];
    const float* vw     = (const float*)d_in[13];
    const float* Wxc    = (const float*)d_in[14];
    const float* bxc    = (const float*)d_in[15];
    const float* Wih    = (const float*)d_in[16];
    const float* Whh    = (const float*)d_in[17];
    const float* bih    = (const float*)d_in[18];
    const float* bhh    = (const float*)d_in[19];
    const float* Wpg    = (const float*)d_in[20];
    const float* bpg    = (const float*)d_in[21];
    const float* Wo1    = (const float*)d_in[22];
    const float* bo1    = (const float*)d_in[23];
    const float* Wo2    = (const float*)d_in[24];
    const float* bo2    = (const float*)d_in[25];
    float* out = (float*)d_out;

    float* scr = nullptr;
    cudaGetSymbolAddress((void**)&scr, g_scratch);
    float* xin    = scr + OFF_XIN;
    float* x      = scr + OFF_X;
    float* gates  = scr + OFF_GATES;
    float* sthat  = scr + OFF_STHAT;
    float* decfea = scr + OFF_DECFEA;
    float* scores = scr + OFF_SCORES;
    float* hct    = scr + OFF_HCT;
    float* out1   = scr + OFF_OUT1;

    const int SMEM_BIG   = (2 * 128 * 36 + 2 * 128 * 36) * 4;  // 73728
    const int SMEM_SMALL = (2 * 128 * 36 + 2 * 64 * 36) * 4;   // 55296
    cudaFuncSetAttribute(k_mma<4>, cudaFuncAttributeMaxDynamicSharedMemorySize, SMEM_BIG);
    cudaFuncSetAttribute(k_mma<2>, cudaFuncAttributeMaxDynamicSharedMemorySize, SMEM_SMALL);

    // x = concat(c_t_1, emb[y]) @ W_xc^T + b_xc
    k_build_xin<<<128, 256>>>(y, ct1, emb, xin);
    k_mma<2><<<2, 128, SMEM_SMALL>>>(xin, Wxc, bxc, nullptr, x, 128, 1152, 1152, 128, 0);

    // gates = x @ W_ih^T + (b_ih + b_hh) + h0 @ W_hh^T
    k_mma<2><<<32, 128, SMEM_SMALL>>>(x,  Wih, bih, bhh, gates, 2048, 128, 128, 2048, 0);
    k_mma<2><<<32, 128, SMEM_SMALL>>>(h0, Whh, nullptr, nullptr, gates, 2048, 512, 512, 2048, 1);
    k_lstm<<<128, 512>>>(gates, c0, out, sthat, hct);

    // attention
    k_mma<2><<<16, 128, SMEM_SMALL>>>(sthat, Wdp, bdp, nullptr, decfea, 1024, 1024, 1024, 1024, 0);
    k_attn_scores<<<dim3(128, 25), 256>>>(encf, decfea, cov, Wc, vw, scores);
    k_attn_softmax<<<128, 128>>>(scores, mask, cov, out);
    k_context<<<dim3(128, 4), 256>>>(encout, out, out, hct);

    // p_gen
    k_pgen<<<128, 256>>>(out, sthat, x, Wpg, bpg, out);

    // vocab distribution (logits straight into final_dist region)
    k_mma<2><<<8, 128, SMEM_SMALL>>>(hct, Wo1, bo1, nullptr, out1, 512, 1536, 1536, 512, 0);
    k_mma<4><<<391, 256, SMEM_BIG>>>(out1, Wo2, bo2, nullptr, out, 50000, 512, 512, 50000, 0);
    k_vocab_softmax<<<128, 256>>>(out);

    // pointer mixing
    k_scatter<<<200, 256>>>(ebev, out, out);
}

// round 17
// speedup vs baseline: 1.7062x; 1.7062x over previous
#include <cuda_runtime.h>
#include <math.h>
#include <stdint.h>

#define Bn   128
#define Tn   400
#define Vn   50000
#define EPSf 1e-12f

// ---- output layout (floats): concat of reference returns ----
#define O_FINAL 0
#define O_H     6400000
#define O_C     6465536
#define O_CT    6531072
#define O_ATTN  6662144
#define O_PGEN  6713344
#define O_COV   6713472

// ---- scratch layout: split-K GEMM outputs first (zeroed by one memset) ----
#define OFF_X      0        // [128,128]
#define OFF_GATES  16384    // [128,2048]
#define OFF_DECFEA 278528   // [128,1024]
#define OFF_OUT1   409600   // [128,512]
#define ZERO_FLOATS 475136
#define OFF_XIN    475136   // [128,1152]
#define OFF_STHAT  622592   // [128,1024]
#define OFF_HCT    753664   // [128,1536]
#define OFF_PG     950272   // [128]
#define SCRATCH_FLOATS 950400

__device__ float g_scratch[SCRATCH_FLOATS];

__device__ __forceinline__ float warpReduceSum(float v) {
#pragma unroll
    for (int o = 16; o > 0; o >>= 1) v += __shfl_xor_sync(0xffffffffu, v, o);
    return v;
}
__device__ __forceinline__ float warpReduceMax(float v) {
#pragma unroll
    for (int o = 16; o > 0; o >>= 1) v = fmaxf(v, __shfl_xor_sync(0xffffffffu, v, o));
    return v;
}
__device__ __forceinline__ float sigmoidf_(float x) { return 1.f / (1.f + expf(-x)); }

// fast tanh via MUFU (EX2 + fast div); clamped so __expf can't overflow
__device__ __forceinline__ float ftanh(float x) {
    x = fminf(15.f, fmaxf(-15.f, x));
    float e = __expf(2.f * x);
    return __fdividef(e - 1.f, e + 1.f);
}

__device__ __forceinline__ uint32_t f2tf32(float f) {
    uint32_t u;
    asm("cvt.rna.tf32.f32 %0, %1;" : "=r"(u) : "f"(f));
    return u;
}

__device__ __forceinline__ void mma_tf32(float* c, const uint32_t* a, const uint32_t* b) {
    asm("mma.sync.aligned.m16n8k8.row.col.f32.tf32.tf32.f32 "
        "{%0,%1,%2,%3}, {%4,%5,%6,%7}, {%8,%9}, {%0,%1,%2,%3};"
        : "+f"(c[0]), "+f"(c[1]), "+f"(c[2]), "+f"(c[3])
        : "r"(a[0]), "r"(a[1]), "r"(a[2]), "r"(a[3]), "r"(b[0]), "r"(b[1]));
}

// ============ split-K tf32 GEMM core (WN=2, 128 threads, 128x64 tile) ============
// C[128,N] += A[128,kc0*32 : kc1*32] @ B^T slice; bias added only when kc0==0.
// N must be a multiple of 64. Results accumulated via atomicAdd (C pre-zeroed).
__device__ __forceinline__ void mma_sk_core(
        const float* __restrict__ A, const float* __restrict__ B,
        const float* __restrict__ b1, const float* __restrict__ b2,
        float* __restrict__ C, int N, int K, int lda, int ldc,
        int kc0, int kc1, uint32_t* sm) {
    const int tid = threadIdx.x;
    const int wid = tid >> 5, lane = tid & 31;
    const int g = lane >> 2, t = lane & 3;
    const int n0 = blockIdx.x * 64;
    const int mw = (wid >> 1) * 64;
    const int nw = (wid & 1) * 32;
    uint32_t* As = sm;                    // [2][128][36]
    uint32_t* Bs = sm + 2 * 128 * 36;     // [2][64][36]

    float acc[4][4][4] = {};
    float4 apf[8], bpf[4];

#define SK_GLOAD(KC)                                                           \
    {                                                                          \
        const float* Ap = A + (KC) * 32;                                       \
        _Pragma("unroll")                                                      \
        for (int i = 0; i < 8; i++) {                                          \
            int e = tid + i * 128;                                             \
            int r = e >> 3, c4 = (e & 7) * 4;                                  \
            apf[i] = *(const float4*)(Ap + (long long)r * lda + c4);           \
        }                                                                      \
        const float* Bp = B + (KC) * 32;                                       \
        _Pragma("unroll")                                                      \
        for (int i = 0; i < 4; i++) {                                          \
            int e = tid + i * 128;                                             \
            int r = e >> 3, c4 = (e & 7) * 4;                                  \
            bpf[i] = *(const float4*)(Bp + (long long)(n0 + r) * K + c4);      \
        }                                                                      \
    }
#define SK_SSTORE(BUF)                                                         \
    {                                                                          \
        uint32_t* Asb = As + (BUF) * (128 * 36);                               \
        _Pragma("unroll")                                                      \
        for (int i = 0; i < 8; i++) {                                          \
            int e = tid + i * 128;                                             \
            int r = e >> 3, c4 = (e & 7) * 4;                                  \
            uint4 u = make_uint4(f2tf32(apf[i].x), f2tf32(apf[i].y),           \
                                 f2tf32(apf[i].z), f2tf32(apf[i].w));          \
            *(uint4*)(Asb + r * 36 + c4) = u;                                  \
        }                                                                      \
        uint32_t* Bsb = Bs + (BUF) * (64 * 36);                                \
        _Pragma("unroll")                                                      \
        for (int i = 0; i < 4; i++) {                                          \
            int e = tid + i * 128;                                             \
            int r = e >> 3, c4 = (e & 7) * 4;                                  \
            uint4 u = make_uint4(f2tf32(bpf[i].x), f2tf32(bpf[i].y),           \
                                 f2tf32(bpf[i].z), f2tf32(bpf[i].w));          \
            *(uint4*)(Bsb + r * 36 + c4) = u;                                  \
        }                                                                      \
    }

    SK_GLOAD(kc0);
    SK_SSTORE(0);
    __syncthreads();
    int buf = 0;
    for (int kc = kc0; kc < kc1; kc++) {
        bool more = (kc + 1 < kc1);
        if (more) SK_GLOAD(kc + 1);
        const uint32_t* Asb = As + buf * (128 * 36);
        const uint32_t* Bsb = Bs + buf * (64 * 36);
#pragma unroll
        for (int kk = 0; kk < 32; kk += 8) {
            uint32_t af[4][4], bf[4][2];
#pragma unroll
            for (int mt = 0; mt < 4; mt++) {
                const uint32_t* p = Asb + (mw + mt * 16 + g) * 36 + kk + t;
                af[mt][0] = p[0];
                af[mt][2] = p[4];
                af[mt][1] = p[8 * 36];
                af[mt][3] = p[8 * 36 + 4];
            }
#pragma unroll
            for (int nt = 0; nt < 4; nt++) {
                const uint32_t* p = Bsb + (nw + nt * 8 + g) * 36 + kk + t;
                bf[nt][0] = p[0];
                bf[nt][1] = p[4];
            }
#pragma unroll
            for (int mt = 0; mt < 4; mt++)
#pragma unroll
                for (int nt = 0; nt < 4; nt++)
                    mma_tf32(acc[mt][nt], af[mt], bf[nt]);
        }
        if (more) {
            SK_SSTORE(buf ^ 1);
            __syncthreads();
        }
        buf ^= 1;
    }

    const bool addb = (kc0 == 0);
#pragma unroll
    for (int mt = 0; mt < 4; mt++) {
        int r = mw + mt * 16 + g;
#pragma unroll
        for (int nt = 0; nt < 4; nt++) {
            int c = n0 + nw + nt * 8 + 2 * t;
            float bb0 = 0.f, bb1 = 0.f;
            if (addb) {
                bb0 = (b1 ? b1[c] : 0.f) + (b2 ? b2[c] : 0.f);
                bb1 = (b1 ? b1[c + 1] : 0.f) + (b2 ? b2[c + 1] : 0.f);
            }
            long long i0 = (long long)r * ldc + c;
            long long i1 = (long long)(r + 8) * ldc + c;
            atomicAdd(&C[i0],     acc[mt][nt][0] + bb0);
            atomicAdd(&C[i0 + 1], acc[mt][nt][1] + bb1);
            atomicAdd(&C[i1],     acc[mt][nt][2] + bb0);
            atomicAdd(&C[i1 + 1], acc[mt][nt][3] + bb1);
        }
    }
#undef SK_GLOAD
#undef SK_SSTORE
}

__global__ __launch_bounds__(128) void k_mma_sk(
        const float* __restrict__ A, const float* __restrict__ B,
        const float* __restrict__ b1, const float* __restrict__ b2,
        float* __restrict__ C, int N, int K, int lda, int ldc, int cps) {
    extern __shared__ uint32_t sm[];
    int nch = K >> 5;
    int kc0 = blockIdx.y * cps;
    int kc1 = min(kc0 + cps, nch);
    mma_sk_core(A, B, b1, b2, C, N, K, lda, ldc, kc0, kc1, sm);
}

// both gates GEMMs fused into one launch via blockIdx.z
__global__ __launch_bounds__(128) void k_gates_sk(
        const float* __restrict__ x, const float* __restrict__ h0,
        const float* __restrict__ Wih, const float* __restrict__ Whh,
        const float* __restrict__ bih, const float* __restrict__ bhh,
        float* __restrict__ gates) {
    extern __shared__ uint32_t sm[];
    if (blockIdx.z == 0)
        mma_sk_core(x, Wih, bih, bhh, gates, 2048, 128, 128, 2048,
                    blockIdx.y, blockIdx.y + 1, sm);
    else
        mma_sk_core(h0, Whh, nullptr, nullptr, gates, 2048, 512, 512, 2048,
                    blockIdx.y * 4, blockIdx.y * 4 + 4, sm);
}

// ============ big tf32 GEMM (non-split, WN warps along N) ============
template<int WN>
__global__ void __launch_bounds__(WN * 64) k_mma(
        const float* __restrict__ A, const float* __restrict__ B,
        const float* __restrict__ bias1, float* __restrict__ C,
        int N, int K, int lda, int ldc) {
    constexpr int NTHR = WN * 64;
    constexpr int TN   = WN * 32;
    constexpr int AF4  = 1024 / NTHR;
    constexpr int BF4  = (TN * 8) / NTHR;

    extern __shared__ uint32_t sm[];
    uint32_t* As = sm;
    uint32_t* Bs = sm + 2 * 128 * 36;

    const int tid  = threadIdx.x;
    const int wid  = tid >> 5, lane = tid & 31;
    const int g    = lane >> 2, t = lane & 3;
    const int n0   = blockIdx.x * TN;
    const int mw   = (wid / WN) * 64;
    const int nw   = (wid % WN) * 32;

    float acc[4][4][4] = {};
    float4 apf[AF4], bpf[BF4];
    const int nchunks = K >> 5;

#define GLOAD(KC)                                                              \
    {                                                                          \
        const float* Ap = A + (KC) * 32;                                       \
        _Pragma("unroll")                                                      \
        for (int i = 0; i < AF4; i++) {                                        \
            int e = tid + i * NTHR;                                            \
            int r = e >> 3, c4 = (e & 7) * 4;                                  \
            apf[i] = *(const float4*)(Ap + (long long)r * lda + c4);           \
        }                                                                      \
        const float* Bp = B + (KC) * 32;                                       \
        _Pragma("unroll")                                                      \
        for (int i = 0; i < BF4; i++) {                                        \
            int e = tid + i * NTHR;                                            \
            int r = e >> 3, c4 = (e & 7) * 4;                                  \
            int rg = n0 + r;                                                   \
            bpf[i] = (rg < N) ? *(const float4*)(Bp + (long long)rg * K + c4)  \
                              : make_float4(0.f, 0.f, 0.f, 0.f);               \
        }                                                                      \
    }
#define SSTORE(BUF)                                                            \
    {                                                                          \
        uint32_t* Asb = As + (BUF) * (128 * 36);                               \
        _Pragma("unroll")                                                      \
        for (int i = 0; i < AF4; i++) {                                        \
            int e = tid + i * NTHR;                                            \
            int r = e >> 3, c4 = (e & 7) * 4;                                  \
            uint4 u = make_uint4(f2tf32(apf[i].x), f2tf32(apf[i].y),           \
                                 f2tf32(apf[i].z), f2tf32(apf[i].w));          \
            *(uint4*)(Asb + r * 36 + c4) = u;                                  \
        }                                                                      \
        uint32_t* Bsb = Bs + (BUF) * (TN * 36);                                \
        _Pragma("unroll")                                                      \
        for (int i = 0; i < BF4; i++) {                                        \
            int e = tid + i * NTHR;                                            \
            int r = e >> 3, c4 = (e & 7) * 4;                                  \
            uint4 u = make_uint4(f2tf32(bpf[i].x), f2tf32(bpf[i].y),           \
                                 f2tf32(bpf[i].z), f2tf32(bpf[i].w));          \
            *(uint4*)(Bsb + r * 36 + c4) = u;                                  \
        }                                                                      \
    }

    GLOAD(0);
    SSTORE(0);
    __syncthreads();

    int buf = 0;
    for (int kc = 0; kc < nchunks; kc++) {
        bool more = (kc + 1 < nchunks);
        if (more) GLOAD(kc + 1);

        const uint32_t* Asb = As + buf * (128 * 36);
        const uint32_t* Bsb = Bs + buf * (TN * 36);
#pragma unroll
        for (int kk = 0; kk < 32; kk += 8) {
            uint32_t af[4][4], bf[4][2];
#pragma unroll
            for (int mt = 0; mt < 4; mt++) {
                const uint32_t* p = Asb + (mw + mt * 16 + g) * 36 + kk + t;
                af[mt][0] = p[0];
                af[mt][2] = p[4];
                af[mt][1] = p[8 * 36];
                af[mt][3] = p[8 * 36 + 4];
            }
#pragma unroll
            for (int nt = 0; nt < 4; nt++) {
                const uint32_t* p = Bsb + (nw + nt * 8 + g) * 36 + kk + t;
                bf[nt][0] = p[0];
                bf[nt][1] = p[4];
            }
#pragma unroll
            for (int mt = 0; mt < 4; mt++)
#pragma unroll
                for (int nt = 0; nt < 4; nt++)
                    mma_tf32(acc[mt][nt], af[mt], bf[nt]);
        }
        if (more) {
            SSTORE(buf ^ 1);
            __syncthreads();
        }
        buf ^= 1;
    }

#pragma unroll
    for (int mt = 0; mt < 4; mt++) {
        int r = mw + mt * 16 + g;
#pragma unroll
        for (int nt = 0; nt < 4; nt++) {
            int c = n0 + nw + nt * 8 + 2 * t;
            if (c + 1 < N) {
                float b0 = bias1[c], b1 = bias1[c + 1];
                long long i0 = (long long)r * ldc + c;
                long long i1 = (long long)(r + 8) * ldc + c;
                *(float2*)&C[i0] = make_float2(acc[mt][nt][0] + b0, acc[mt][nt][1] + b1);
                *(float2*)&C[i1] = make_float2(acc[mt][nt][2] + b0, acc[mt][nt][3] + b1);
            } else if (c < N) {
                float b0 = bias1[c];
                C[(long long)r * ldc + c] = acc[mt][nt][0] + b0;
                C[(long long)(r + 8) * ldc + c] = acc[mt][nt][2] + b0;
            }
        }
    }
#undef GLOAD
#undef SSTORE
}

// ---- xin = concat(c_t_1, emb[y]) ----
__global__ void k_build_xin(const int* __restrict__ y, const float* __restrict__ ct1,
                            const float* __restrict__ emb, float* __restrict__ xin) {
    int b = blockIdx.x;
    int yy = y[b];
    for (int i = threadIdx.x; i < 1152; i += blockDim.x)
        xin[b * 1152 + i] = (i < 1024) ? ct1[b * 1024 + i] : emb[yy * 128 + (i - 1024)];
}

// ---- LSTM cell + p_gen partial (sthat & x parts, plain store) ----
__global__ __launch_bounds__(512) void k_lstm(const float* __restrict__ gates,
                                              const float* __restrict__ c0,
                                              const float* __restrict__ x,
                                              const float* __restrict__ Wpg,
                                              const float* __restrict__ bpg,
                                              float* __restrict__ out,
                                              float* __restrict__ sthat,
                                              float* __restrict__ hct,
                                              float* __restrict__ pg) {
    __shared__ float red[16];
    int b = blockIdx.x, j = threadIdx.x;
    const float* g = gates + b * 2048;
    float ig = g[j], fg = g[512 + j], gg = g[1024 + j], og = g[1536 + j];
    float c = sigmoidf_(fg) * c0[b * 512 + j] + sigmoidf_(ig) * tanhf(gg);
    float h = sigmoidf_(og) * tanhf(c);
    out[O_H + b * 512 + j] = h;
    out[O_C + b * 512 + j] = c;
    sthat[b * 1024 + j] = h;
    sthat[b * 1024 + 512 + j] = c;
    hct[b * 1536 + j] = h;

    float local = h * Wpg[1024 + j] + c * Wpg[1536 + j];
    if (j < 128) local += x[b * 128 + j] * Wpg[2048 + j];
    local = warpReduceSum(local);
    if ((j & 31) == 0) red[j >> 5] = local;
    __syncthreads();
    if (j == 0) {
        float s = 0.f;
#pragma unroll
        for (int w = 0; w < 16; w++) s += red[w];
        pg[b] = s + bpg[0];
    }
}

// ---- fused attention scores + softmax + mask renorm + coverage ----
__global__ __launch_bounds__(512) void k_attn(const float* __restrict__ encf,
                                              const float* __restrict__ decfea,
                                              const float* __restrict__ cov,
                                              const float* __restrict__ Wc,
                                              const float* __restrict__ vw,
                                              const float* __restrict__ mask,
                                              float* __restrict__ out) {
    __shared__ float4 df[256], wc4[256], vv4[256];
    __shared__ float sc[400];
    __shared__ float red[16];
    int b = blockIdx.x, tid = threadIdx.x;
    if (tid < 256) {
        df[tid] = ((const float4*)(decfea + b * 1024))[tid];
    } else {
        int i = tid - 256;
        wc4[i] = ((const float4*)Wc)[i];
        vv4[i] = ((const float4*)vw)[i];
    }
    __syncthreads();

    int w = tid >> 5, lane = tid & 31;
    for (int i = 0; i < 25; i++) {
        int t = w * 25 + i;
        float cv = cov[b * 400 + t];
        const float4* ef = (const float4*)(encf + ((long long)b * 400 + t) * 1024);
        float local = 0.f;
#pragma unroll
        for (int j = 0; j < 8; j++) {
            int idx = lane + j * 32;
            float4 e4 = ef[idx];
            float4 d4 = df[idx], w4 = wc4[idx], v4 = vv4[idx];
            local += ftanh(e4.x + d4.x + cv * w4.x) * v4.x;
            local += ftanh(e4.y + d4.y + cv * w4.y) * v4.y;
            local += ftanh(e4.z + d4.z + cv * w4.z) * v4.z;
            local += ftanh(e4.w + d4.w + cv * w4.w) * v4.w;
        }
        local = warpReduceSum(local);
        if (lane == 0) sc[t] = local;
    }
    __syncthreads();

    // softmax over 400 (one element per thread for tid<400)
    float v = (tid < 400) ? sc[tid] : -1e30f;
    float mx = warpReduceMax(v);
    if (lane == 0) red[w] = mx;
    __syncthreads();
    mx = red[0];
#pragma unroll
    for (int i = 1; i < 16; i++) mx = fmaxf(mx, red[i]);
    __syncthreads();

    float e = (tid < 400) ? __expf(v - mx) : 0.f;
    float s = warpReduceSum(e);
    if (lane == 0) red[w] = s;
    __syncthreads();
    float denom = 0.f;
#pragma unroll
    for (int i = 0; i < 16; i++) denom += red[i];
    __syncthreads();

    float msk = (tid < 400) ? mask[b * 400 + tid] : 0.f;
    float m2 = e / denom * msk;
    float s2 = warpReduceSum(m2);
    if (lane == 0) red[w] = s2;
    __syncthreads();
    float denom2 = EPSf;
#pragma unroll
    for (int i = 0; i < 16; i++) denom2 += red[i];

    if (tid < 400) {
        float a = m2 / denom2;
        out[O_ATTN + b * 400 + tid] = a;
        out[O_COV + b * 400 + tid] = cov[b * 400 + tid] + a;
    }
}

// ---- context vector + p_gen ct-partial (atomicAdd) ----
__global__ __launch_bounds__(256) void k_context(const float* __restrict__ encout,
                                                 const float* __restrict__ outbuf,
                                                 const float* __restrict__ Wpg,
                                                 float* __restrict__ out,
                                                 float* __restrict__ hct,
                                                 float* __restrict__ pg) {
    __shared__ float at[400];
    __shared__ float red[8];
    int b = blockIdx.x, tid = threadIdx.x;
    for (int i = tid; i < 400; i += 256) at[i] = outbuf[O_ATTN + b * 400 + i];
    __syncthreads();
    int n = blockIdx.y * 256 + tid;
    const float* ep = encout + (long long)b * 400 * 1024 + n;
    float a0 = 0.f, a1 = 0.f, a2 = 0.f, a3 = 0.f;
    for (int t = 0; t < 400; t += 4) {
        a0 += at[t + 0] * ep[(t + 0) * 1024];
        a1 += at[t + 1] * ep[(t + 1) * 1024];
        a2 += at[t + 2] * ep[(t + 2) * 1024];
        a3 += at[t + 3] * ep[(t + 3) * 1024];
    }
    float acc = (a0 + a1) + (a2 + a3);
    out[O_CT + b * 1024 + n] = acc;
    hct[b * 1536 + 512 + n] = acc;

    float local = acc * Wpg[n];
    local = warpReduceSum(local);
    if ((tid & 31) == 0) red[tid >> 5] = local;
    __syncthreads();
    if (tid == 0) {
        float s = 0.f;
#pragma unroll
        for (int w = 0; w < 8; w++) s += red[w];
        atomicAdd(&pg[b], s);
    }
}

// ---- vocab softmax (p_gen sigmoid + online max/sum + scale) + pointer scatter ----
__global__ __launch_bounds__(256) void k_vocab(float* __restrict__ out,
                                               const int* __restrict__ ebev,
                                               const float* __restrict__ pg) {
    __shared__ float rm[8], rs[8];
    int b = blockIdx.x, tid = threadIdx.x;
    float* row = out + (long long)b * Vn;
    float p = sigmoidf_(pg[b]);
    if (tid == 0) out[O_PGEN + b] = p;

    const float4* r4 = (const float4*)row;
    float m = -1e30f, s = 0.f;
    for (int i = tid; i < 12500; i += 256) {
        float4 v = r4[i];
        float lm = fmaxf(fmaxf(v.x, v.y), fmaxf(v.z, v.w));
        if (lm > m) { s *= __expf(m - lm); m = lm; }
        s += __expf(v.x - m) + __expf(v.y - m) + __expf(v.z - m) + __expf(v.w - m);
    }
#pragma unroll
    for (int o = 16; o > 0; o >>= 1) {
        float m2 = __shfl_xor_sync(0xffffffffu, m, o);
        float s2 = __shfl_xor_sync(0xffffffffu, s, o);
        float M = fmaxf(m, m2);
        s = s * __expf(m - M) + s2 * __expf(m2 - M);
        m = M;
    }
    if ((tid & 31) == 0) { rm[tid >> 5] = m; rs[tid >> 5] = s; }
    __syncthreads();
    float M = rm[0];
#pragma unroll
    for (int w = 1; w < 8; w++) M = fmaxf(M, rm[w]);
    float S = 0.f;
#pragma unroll
    for (int w = 0; w < 8; w++) S += rs[w] * __expf(rm[w] - M);

    float scale = p / S;
    float4* w4 = (float4*)row;
    for (int i = tid; i < 12500; i += 256) {
        float4 v = r4[i];
        v.x = __expf(v.x - M) * scale;
        v.y = __expf(v.y - M) * scale;
        v.z = __expf(v.z - M) * scale;
        v.w = __expf(v.w - M) * scale;
        w4[i] = v;
    }
    __syncthreads();

    // pointer scatter for this row
    float omp = 1.f - p;
    for (int t = tid; t < 400; t += 256) {
        float add = omp * out[O_ATTN + b * 400 + t];
        atomicAdd(&row[ebev[b * 400 + t]], add);
    }
}

extern "C" void kernel_launch(void* const* d_in, const int* in_sizes, int n_in,
                              void* d_out, int out_size) {
    const int*   y      = (const int*)d_in[0];
    const float* h0     = (const float*)d_in[1];
    const float* c0     = (const float*)d_in[2];
    const float* ct1    = (const float*)d_in[3];
    const float* encout = (const float*)d_in[4];
    const float* encf   = (const float*)d_in[5];
    const float* mask   = (const float*)d_in[6];
    const int*   ebev   = (const int*)d_in[7];
    const float* cov    = (const float*)d_in[8];
    const float* emb    = (const float*)d_in[9];
    const float* Wc     = (const float*)d_in[10];
    const float* Wdp    = (const float*)d_in[11];
    const float* bdp    = (const float*)d_in[12];
    const float* vw     = (const float*)d_in[13];
    const float* Wxc    = (const float*)d_in[14];
    const float* bxc    = (const float*)d_in[15];
    const float* Wih    = (const float*)d_in[16];
    const float* Whh    = (const float*)d_in[17];
    const float* bih    = (const float*)d_in[18];
    const float* bhh    = (const float*)d_in[19];
    const float* Wpg    = (const float*)d_in[20];
    const float* bpg    = (const float*)d_in[21];
    const float* Wo1    = (const float*)d_in[22];
    const float* bo1    = (const float*)d_in[23];
    const float* Wo2    = (const float*)d_in[24];
    const float* bo2    = (const float*)d_in[25];
    float* out = (float*)d_out;

    float* scr = nullptr;
    cudaGetSymbolAddress((void**)&scr, g_scratch);
    float* x      = scr + OFF_X;
    float* gates  = scr + OFF_GATES;
    float* decfea = scr + OFF_DECFEA;
    float* out1   = scr + OFF_OUT1;
    float* xin    = scr + OFF_XIN;
    float* sthat  = scr + OFF_STHAT;
    float* hct    = scr + OFF_HCT;
    float* pg     = scr + OFF_PG;

    const int SMEM_BIG = (2 * 128 * 36 + 2 * 128 * 36) * 4;  // 73728
    const int SMEM_SK  = (2 * 128 * 36 + 2 * 64 * 36) * 4;   // 55296
    cudaFuncSetAttribute(k_mma<4>, cudaFuncAttributeMaxDynamicSharedMemorySize, SMEM_BIG);
    cudaFuncSetAttribute(k_mma_sk, cudaFuncAttributeMaxDynamicSharedMemorySize, SMEM_SK);
    cudaFuncSetAttribute(k_gates_sk, cudaFuncAttributeMaxDynamicSharedMemorySize, SMEM_SK);

    // zero all split-K GEMM outputs (x, gates, decfea, out1) in one memset
    cudaMemsetAsync(scr, 0, ZERO_FLOATS * sizeof(float));

    // x = concat(c_t_1, emb[y]) @ W_xc^T + b_xc   (36 chunks, 12 splits x 3)
    k_build_xin<<<128, 256>>>(y, ct1, emb, xin);
    k_mma_sk<<<dim3(2, 12), 128, SMEM_SK>>>(xin, Wxc, bxc, nullptr, x, 128, 1152, 1152, 128, 3);

    // gates = x @ W_ih^T + (b_ih+b_hh) + h0 @ W_hh^T  (fused, z picks the GEMM)
    k_gates_sk<<<dim3(32, 4, 2), 128, SMEM_SK>>>(x, h0, Wih, Whh, bih, bhh, gates);
    k_lstm<<<128, 512>>>(gates, c0, x, Wpg, bpg, out, sthat, hct, pg);

    // attention
    k_mma_sk<<<dim3(16, 8), 128, SMEM_SK>>>(sthat, Wdp, bdp, nullptr, decfea, 1024, 1024, 1024, 1024, 4);
    k_attn<<<128, 512>>>(encf, decfea, cov, Wc, vw, mask, out);
    k_context<<<dim3(128, 4), 256>>>(encout, out, Wpg, out, hct, pg);

    // vocab distribution
    k_mma_sk<<<dim3(8, 12), 128, SMEM_SK>>>(hct, Wo1, bo1, nullptr, out1, 512, 1536, 1536, 512, 4);
    k_mma<4><<<391, 256, SMEM_BIG>>>(out1, Wo2, bo2, out, 50000, 512, 512, 50000);

    // softmax + p_gen scaling + pointer scatter (fused)
    k_vocab<<<128, 256>>>(out, ebev, pg);
}